// round 12
// baseline (speedup 1.0000x reference)
#include <cuda_runtime.h>
#include <cuda_bf16.h>
#include <cstdint>
#include <cstddef>

#define NN 100000
#define EE 800000
#define DD 128

// ---------------- scratch (device globals; no allocation allowed) -------------
__device__ float g_h[NN * DD];
__device__ float g_xl[NN * DD];
__device__ float g_xr[NN * DD];
__device__ float g_res[NN * DD];
__device__ float g_agg[NN * DD];
__device__ int   g_deg[NN];
__device__ int   g_rowptr[NN + 1];
__device__ int   g_cursor[NN];
__device__ int   g_csrc[EE];
__device__ int   g_blocksums[256];
__device__ int   g_blockoff[256];
#define CPB 592
__device__ float g_colpart[CPB * DD];
__device__ float g_colmean[DD];

// preconverted weights: 9 matrices x (hi,lo) x [128 rows x 136 bf16] padded image
#define LDSB 136
#define RSB  (LDSB * 2)                 // 272 bytes per row
#define BTILE_B (128 * RSB)             // 34816 bytes per B tile
#define WIMG_ELEMS (128 * LDSB)         // 17408 bf16 per tile
__device__ __nv_bfloat16 g_wconv[9 * 2 * WIMG_ELEMS];

// ---------------- CSR build ---------------------------------------------------
__global__ void zero_deg_k() {
    int i = blockIdx.x * blockDim.x + threadIdx.x;
    if (i < NN) g_deg[i] = 0;
}
__global__ void hist_k(const int* __restrict__ ei) {
    int e = blockIdx.x * blockDim.x + threadIdx.x;
    if (e < EE) atomicAdd(&g_deg[ei[EE + e]], 1);
}

#define SC 512
#define SB ((NN + SC - 1) / SC)   // 196

__global__ void scan1_k() {
    __shared__ int s[SC];
    int b = blockIdx.x, t = threadIdx.x;
    int i = b * SC + t;
    int v = (i < NN) ? g_deg[i] : 0;
    s[t] = v;
    __syncthreads();
    for (int off = 1; off < SC; off <<= 1) {
        int x = (t >= off) ? s[t - off] : 0;
        __syncthreads();
        s[t] += x;
        __syncthreads();
    }
    if (i < NN) g_rowptr[i] = s[t] - v;
    if (t == SC - 1) g_blocksums[b] = s[t];
}

__global__ void scan2_k() {
    __shared__ int s[256];
    int t = threadIdx.x;
    int v = (t < SB) ? g_blocksums[t] : 0;
    s[t] = v;
    __syncthreads();
    for (int off = 1; off < 256; off <<= 1) {
        int x = (t >= off) ? s[t - off] : 0;
        __syncthreads();
        s[t] += x;
        __syncthreads();
    }
    if (t < SB) g_blockoff[t] = s[t] - v;
    if (t == 255) g_rowptr[NN] = s[255];
}

__global__ void scan3_k() {
    int b = blockIdx.x, t = threadIdx.x;
    int i = b * SC + t;
    if (i < NN) {
        int v = g_rowptr[i] + g_blockoff[b];
        g_rowptr[i] = v;
        g_cursor[i] = v;
    }
}

__global__ void scatter_k(const int* __restrict__ ei) {
    int e = blockIdx.x * blockDim.x + threadIdx.x;
    if (e < EE) {
        int s = ei[e];
        int d = ei[EE + e];
        int pos = atomicAdd(&g_cursor[d], 1);
        g_csrc[pos] = s;
    }
}

// ---------------- helpers ------------------------------------------------------
__device__ __forceinline__ uint32_t smem_u32(const void* p) {
    uint32_t a;
    asm("{ .reg .u64 t; cvta.to.shared.u64 t, %1; cvt.u32.u64 %0, t; }" : "=r"(a) : "l"(p));
    return a;
}

__device__ __forceinline__ void ldm_x4(uint32_t* r, uint32_t addr) {
    asm volatile("ldmatrix.sync.aligned.m8n8.x4.shared.b16 {%0,%1,%2,%3}, [%4];"
                 : "=r"(r[0]), "=r"(r[1]), "=r"(r[2]), "=r"(r[3]) : "r"(addr));
}

__device__ __forceinline__ void mma16816(float* c, const uint32_t* a, uint32_t b0, uint32_t b1) {
    asm volatile(
        "mma.sync.aligned.m16n8k16.row.col.f32.bf16.bf16.f32 "
        "{%0,%1,%2,%3}, {%4,%5,%6,%7}, {%8,%9}, {%0,%1,%2,%3};"
        : "+f"(c[0]), "+f"(c[1]), "+f"(c[2]), "+f"(c[3])
        : "r"(a[0]), "r"(a[1]), "r"(a[2]), "r"(a[3]), "r"(b0), "r"(b1));
}

__device__ __forceinline__ void split8(const float* v, uint4& hi, uint4& lo) {
    uint32_t h[4], l[4];
    #pragma unroll
    for (int p = 0; p < 4; p++) {
        float a = v[2 * p], b = v[2 * p + 1];
        __nv_bfloat16 ha = __float2bfloat16_rn(a), hb = __float2bfloat16_rn(b);
        float ra = a - __bfloat162float(ha), rb = b - __bfloat162float(hb);
        __nv_bfloat16 la = __float2bfloat16_rn(ra);
        __nv_bfloat16 lb = __float2bfloat16_rn(rb);
        h[p] = ((uint32_t)__bfloat16_as_ushort(hb) << 16) | __bfloat16_as_ushort(ha);
        l[p] = ((uint32_t)__bfloat16_as_ushort(lb) << 16) | __bfloat16_as_ushort(la);
    }
    hi = make_uint4(h[0], h[1], h[2], h[3]);
    lo = make_uint4(l[0], l[1], l[2], l[3]);
}

// ---------------- W pre-conversion: 9 matrices -> padded transposed bf16 image -
__global__ void wconv_k(const float* __restrict__ w0, const float* __restrict__ wl,
                        const float* __restrict__ wr, const float* __restrict__ wres) {
    int mat = blockIdx.x;   // 0: w_in, 1..3: Wl, 4..6: Wr, 7..8: Wres
    const float* W;
    if (mat == 0)      W = w0;
    else if (mat <= 3) W = wl + (size_t)(mat - 1) * DD * DD;
    else if (mat <= 6) W = wr + (size_t)(mat - 4) * DD * DD;
    else               W = wres + (size_t)(mat - 7) * DD * DD;

    __nv_bfloat16* hiT = g_wconv + (size_t)mat * 2 * WIMG_ELEMS;
    __nv_bfloat16* loT = hiT + WIMG_ELEMS;
    int tid = threadIdx.x;
    #pragma unroll
    for (int it = 0; it < 8; it++) {
        int t = tid + it * 256;       // 0..2047
        int n = t & 127, c = t >> 7;  // col n, 8-wide k chunk
        int k0 = c * 8;
        float v[8];
        #pragma unroll
        for (int q = 0; q < 8; q++) v[q] = W[(size_t)(k0 + q) * 128 + n];
        uint4 hi, lo;
        split8(v, hi, lo);
        size_t off = (size_t)n * LDSB + k0;
        *(uint4*)(hiT + off) = hi;
        *(uint4*)(loT + off) = lo;
    }
}

// ---------------- HMMA GEMM: C[M,128] = A[M,128] @ W[128,128] (+bias) ---------
// bf16 hi/lo split, 3 compensated products, fp32 accumulators (mma.sync).
// 256-row A tile @ 512 threads; W tiles copied preconverted.
struct Job { const __nv_bfloat16* Wc; const float* bias; float* out; };

#define RT 256                          // A tile rows
#define ATILE_B (RT * RSB)              // 69632 bytes per A tile (hi or lo)
#define OFF_AHI 0
#define OFF_ALO ATILE_B
#define OFF_BHI (2 * ATILE_B)
#define OFF_BLO (2 * ATILE_B + BTILE_B)
#define GEMM_SMEM (2 * ATILE_B + 2 * BTILE_B)   // 208896 bytes

__global__ void __launch_bounds__(512, 1)
gemm_mma_k(const float* __restrict__ A, Job j0, Job j1, Job j2, int njobs, int M) {
    extern __shared__ char sm[];
    uint32_t smb = smem_u32(sm);
    int tid = threadIdx.x;
    int wid = tid >> 5;
    int lane = tid & 31;
    int rowBase = blockIdx.x * RT;

    // ---- load & split A tile [256 x 128] fp32 -> bf16 hi/lo (once) ----
    #pragma unroll
    for (int it = 0; it < 8; it++) {
        int t = tid + it * 512;       // 0..4095
        int r = t >> 4, c = t & 15;
        int k0 = c * 8;
        float v[8];
        int gr = rowBase + r;
        if (gr < M) {
            *(float4*)(v)     = *(const float4*)(A + (size_t)gr * 128 + k0);
            *(float4*)(v + 4) = *(const float4*)(A + (size_t)gr * 128 + k0 + 4);
        } else {
            #pragma unroll
            for (int q = 0; q < 8; q++) v[q] = 0.f;
        }
        uint4 hi, lo;
        split8(v, hi, lo);
        uint32_t off = (uint32_t)r * RSB + (uint32_t)k0 * 2;
        *(uint4*)(sm + OFF_AHI + off) = hi;
        *(uint4*)(sm + OFF_ALO + off) = lo;
    }

    // warp tiling: 8x2 warps, each 32 rows x 64 cols
    int rm = (wid & 7) * 32;
    int cn = (wid >> 3) * 64;

    // lane-derived ldmatrix source offsets
    int la16 = lane & 15;
    int akoff = (lane >> 4) * 8;
    int bq = lane >> 3;
    int br = lane & 7;
    int brow_add = (bq >> 1) * 8 + br;
    int bkoff = (bq & 1) * 8;
    int g = lane >> 2, tq = lane & 3;

    for (int jj = 0; jj < njobs; jj++) {
        Job jb = (jj == 0) ? j0 : (jj == 1 ? j1 : j2);

        if (jj > 0) __syncthreads();   // previous job's B reads complete

        // ---- copy preconverted W image (hi+lo = 69632 B = 4352 uint4) ----
        {
            const uint4* src = (const uint4*)jb.Wc;      // hi tile then lo tile, contiguous
            uint4* dst = (uint4*)(sm + OFF_BHI);
            for (int idx = tid; idx < 4352; idx += 512)
                dst[idx] = src[idx];
        }
        __syncthreads();

        float acc[2][8][4];
        #pragma unroll
        for (int mt = 0; mt < 2; mt++)
            #pragma unroll
            for (int nt = 0; nt < 8; nt++)
                #pragma unroll
                for (int q = 0; q < 4; q++) acc[mt][nt][q] = 0.f;

        #pragma unroll
        for (int kk = 0; kk < 8; kk++) {
            int k0 = kk * 16;
            uint32_t Ah[2][4], Al[2][4];
            #pragma unroll
            for (int mt = 0; mt < 2; mt++) {
                uint32_t aoff = (uint32_t)(rm + mt * 16 + la16) * RSB + (uint32_t)(k0 + akoff) * 2;
                ldm_x4(Ah[mt], smb + OFF_AHI + aoff);
                ldm_x4(Al[mt], smb + OFF_ALO + aoff);
            }
            uint32_t Bh[4][4], Bl[4][4];
            #pragma unroll
            for (int nt2 = 0; nt2 < 4; nt2++) {
                uint32_t boff = (uint32_t)(cn + nt2 * 16 + brow_add) * RSB + (uint32_t)(k0 + bkoff) * 2;
                ldm_x4(Bh[nt2], smb + OFF_BHI + boff);
                ldm_x4(Bl[nt2], smb + OFF_BLO + boff);
            }
            #pragma unroll
            for (int mt = 0; mt < 2; mt++) {
                #pragma unroll
                for (int nt = 0; nt < 8; nt++) {
                    int nt2 = nt >> 1, hh = (nt & 1) * 2;
                    mma16816(acc[mt][nt], Ah[mt], Bh[nt2][hh], Bh[nt2][hh + 1]);
                    mma16816(acc[mt][nt], Ah[mt], Bl[nt2][hh], Bl[nt2][hh + 1]);
                    mma16816(acc[mt][nt], Al[mt], Bh[nt2][hh], Bh[nt2][hh + 1]);
                }
            }
        }

        // ---- epilogue: accumulator layout -> global (+bias) ----
        #pragma unroll
        for (int mt = 0; mt < 2; mt++) {
            int r0 = rowBase + rm + mt * 16 + g;
            int r1 = r0 + 8;
            #pragma unroll
            for (int nt = 0; nt < 8; nt++) {
                int col = cn + nt * 8 + 2 * tq;
                float bx = 0.f, by = 0.f;
                if (jb.bias) { bx = jb.bias[col]; by = jb.bias[col + 1]; }
                if (r0 < M) {
                    float2 o = {acc[mt][nt][0] + bx, acc[mt][nt][1] + by};
                    *(float2*)(jb.out + (size_t)r0 * 128 + col) = o;
                }
                if (r1 < M) {
                    float2 o = {acc[mt][nt][2] + bx, acc[mt][nt][3] + by};
                    *(float2*)(jb.out + (size_t)r1 * 128 + col) = o;
                }
            }
        }
    }
}

// ---------------- per-dst softmax aggregation (one warp per node) -------------
// Plain exp (logits provably tiny), 4-wide edge unroll: four independent
// gather+shfl+exp chains in flight.
__global__ void agg_k(const float* __restrict__ xl, const float* __restrict__ xr,
                      const float* __restrict__ att, const float* __restrict__ bout) {
    int warp = (blockIdx.x * blockDim.x + threadIdx.x) >> 5;
    int lane = threadIdx.x & 31;
    if (warp >= NN) return;

    const float4 xrv = *(const float4*)(xr + (size_t)warp * 128 + lane * 4);
    const float4 av  = *(const float4*)(att + lane * 4);

    float a0 = 0.f, a1 = 0.f, a2 = 0.f, a3 = 0.f, s = 0.f;

    int beg = g_rowptr[warp];
    int n = g_rowptr[warp + 1] - beg;
    const int* csrc = g_csrc + beg;

    float4 b[4];
    #pragma unroll
    for (int q = 0; q < 4; q++)
        if (q < n) b[q] = *(const float4*)(xl + (size_t)csrc[q] * 128 + lane * 4);

    for (int j = 0; j < n; j += 4) {
        float4 c[4];
        #pragma unroll
        for (int q = 0; q < 4; q++) c[q] = b[q];
        #pragma unroll
        for (int q = 0; q < 4; q++)
            if (j + 4 + q < n) b[q] = *(const float4*)(xl + (size_t)csrc[j + 4 + q] * 128 + lane * 4);

        float p[4];
        #pragma unroll
        for (int q = 0; q < 4; q++) {
            float u0 = c[q].x + xrv.x; u0 = fmaxf(u0, 0.2f * u0);
            float u1 = c[q].y + xrv.y; u1 = fmaxf(u1, 0.2f * u1);
            float u2 = c[q].z + xrv.z; u2 = fmaxf(u2, 0.2f * u2);
            float u3 = c[q].w + xrv.w; u3 = fmaxf(u3, 0.2f * u3);
            p[q] = u0 * av.x + u1 * av.y + u2 * av.z + u3 * av.w;
        }
        #pragma unroll
        for (int off = 1; off <= 4; off <<= 1) {
            #pragma unroll
            for (int q = 0; q < 4; q++)
                p[q] += __shfl_xor_sync(0xffffffffu, p[q], off);
        }
        #pragma unroll
        for (int q = 0; q < 4; q++) {
            float e = (j + q < n) ? __expf(p[q]) : 0.f;
            s  += e;
            a0 += e * c[q].x;
            a1 += e * c[q].y;
            a2 += e * c[q].z;
            a3 += e * c[q].w;
        }
    }

    float inv = 1.f / (s + 1e-16f);
    float4 bo = *(const float4*)(bout + lane * 4);
    float4 o;
    o.x = a0 * inv + bo.x;
    o.y = a1 * inv + bo.y;
    o.z = a2 * inv + bo.z;
    o.w = a3 * inv + bo.w;
    *(float4*)(g_agg + (size_t)warp * 128 + lane * 4) = o;
}

// ---------------- column mean (deterministic two-stage) ------------------------
__global__ void colsum_part_k() {
    int c = threadIdx.x;  // 128 threads, one column each
    float s0 = 0.f, s1 = 0.f, s2 = 0.f, s3 = 0.f;
    int r = blockIdx.x;
    for (; r + 3 * CPB < NN; r += 4 * CPB) {
        s0 += g_agg[(size_t)r * 128 + c];
        s1 += g_agg[(size_t)(r + CPB) * 128 + c];
        s2 += g_agg[(size_t)(r + 2 * CPB) * 128 + c];
        s3 += g_agg[(size_t)(r + 3 * CPB) * 128 + c];
    }
    for (; r < NN; r += CPB) s0 += g_agg[(size_t)r * 128 + c];
    g_colpart[blockIdx.x * 128 + c] = (s0 + s1) + (s2 + s3);
}
__global__ void colsum_fin_k() {
    int c = threadIdx.x;
    float s0 = 0.f, s1 = 0.f, s2 = 0.f, s3 = 0.f;
    int b = 0;
    for (; b + 3 < CPB; b += 4) {
        s0 += g_colpart[b * 128 + c];
        s1 += g_colpart[(b + 1) * 128 + c];
        s2 += g_colpart[(b + 2) * 128 + c];
        s3 += g_colpart[(b + 3) * 128 + c];
    }
    for (; b < CPB; b++) s0 += g_colpart[b * 128 + c];
    g_colmean[c] = ((s0 + s1) + (s2 + s3)) * (1.0f / NN);
}

// ---------------- fused pairnorm + residual + layernorm + relu ----------------
__global__ void epilogue_k(const float* __restrict__ res,
                           const float* __restrict__ lng, const float* __restrict__ lnb,
                           float* __restrict__ out, int relu) {
    int warp = (blockIdx.x * blockDim.x + threadIdx.x) >> 5;
    int lane = threadIdx.x & 31;
    if (warp >= NN) return;

    float4 a4 = *(const float4*)(g_agg + (size_t)warp * 128 + lane * 4);
    float4 cm = *(const float4*)(g_colmean + lane * 4);
    float x0 = a4.x - cm.x, x1 = a4.y - cm.y, x2 = a4.z - cm.z, x3 = a4.w - cm.w;

    float ss = x0 * x0 + x1 * x1 + x2 * x2 + x3 * x3;
    #pragma unroll
    for (int off = 16; off > 0; off >>= 1) ss += __shfl_xor_sync(0xffffffffu, ss, off);
    float l2 = sqrtf(ss) + 1e-6f;
    float sc = 316.2277660168379f / l2;

    float4 r4 = *(const float4*)(res + (size_t)warp * 128 + lane * 4);
    float h0 = x0 * sc + r4.x;
    float h1 = x1 * sc + r4.y;
    float h2 = x2 * sc + r4.z;
    float h3 = x3 * sc + r4.w;

    float sm = h0 + h1 + h2 + h3;
    #pragma unroll
    for (int off = 16; off > 0; off >>= 1) sm += __shfl_xor_sync(0xffffffffu, sm, off);
    float mu = sm * (1.0f / 128.0f);

    float d0 = h0 - mu, d1 = h1 - mu, d2 = h2 - mu, d3 = h3 - mu;
    float sv = d0 * d0 + d1 * d1 + d2 * d2 + d3 * d3;
    #pragma unroll
    for (int off = 16; off > 0; off >>= 1) sv += __shfl_xor_sync(0xffffffffu, sv, off);
    float rs = rsqrtf(sv * (1.0f / 128.0f) + 1e-5f);

    float4 g4 = *(const float4*)(lng + lane * 4);
    float4 b4 = *(const float4*)(lnb + lane * 4);
    float y0 = d0 * rs * g4.x + b4.x;
    float y1 = d1 * rs * g4.y + b4.y;
    float y2 = d2 * rs * g4.z + b4.z;
    float y3 = d3 * rs * g4.w + b4.w;
    if (relu) {
        y0 = fmaxf(y0, 0.f); y1 = fmaxf(y1, 0.f);
        y2 = fmaxf(y2, 0.f); y3 = fmaxf(y3, 0.f);
    }
    float4 o = {y0, y1, y2, y3};
    *(float4*)(out + (size_t)warp * 128 + lane * 4) = o;
}

// ---------------- host orchestration ------------------------------------------
extern "C" void kernel_launch(void* const* d_in, const int* in_sizes, int n_in,
                              void* d_out, int out_size) {
    const float* x     = (const float*)d_in[0];
    const int*   ei    = (const int*)  d_in[1];
    const float* w_in  = (const float*)d_in[2];
    const float* b_in  = (const float*)d_in[3];
    const float* Wl    = (const float*)d_in[4];
    const float* bl    = (const float*)d_in[5];
    const float* Wr    = (const float*)d_in[6];
    const float* att   = (const float*)d_in[7];
    const float* b_out = (const float*)d_in[8];
    const float* Wres  = (const float*)d_in[9];
    const float* bres  = (const float*)d_in[10];
    const float* ln_g  = (const float*)d_in[11];
    const float* ln_b  = (const float*)d_in[12];
    float* out = (float*)d_out;

    cudaFuncSetAttribute(gemm_mma_k, cudaFuncAttributeMaxDynamicSharedMemorySize, GEMM_SMEM);

    float *hp, *xlp, *xrp, *resp;
    cudaGetSymbolAddress((void**)&hp,   g_h);
    cudaGetSymbolAddress((void**)&xlp,  g_xl);
    cudaGetSymbolAddress((void**)&xrp,  g_xr);
    cudaGetSymbolAddress((void**)&resp, g_res);
    __nv_bfloat16* wcp;
    cudaGetSymbolAddress((void**)&wcp, g_wconv);

    const int GX = (NN + RT - 1) / RT;
    const size_t WSTRIDE = 2 * WIMG_ELEMS;

    wconv_k<<<9, 256>>>(w_in, Wl, Wr, Wres);
    zero_deg_k<<<(NN + 255) / 256, 256>>>();

    // input projection: h = x @ w_in + b_in
    {
        Job j0 = {wcp, b_in, hp};
        gemm_mma_k<<<GX, 512, GEMM_SMEM>>>(x, j0, j0, j0, 1, NN);
    }
    // layer-0 GEMM (Wl, Wr)
    {
        Job j0 = {wcp + 1 * WSTRIDE, bl, xlp};
        Job j1 = {wcp + 4 * WSTRIDE, nullptr, xrp};
        gemm_mma_k<<<GX, 512, GEMM_SMEM>>>(hp, j0, j1, j1, 2, NN);
    }

    // CSR build (needed before agg)
    hist_k<<<(EE + 255) / 256, 256>>>(ei);
    scan1_k<<<SB, SC>>>();
    scan2_k<<<1, 256>>>();
    scan3_k<<<SB, SC>>>();
    scatter_k<<<(EE + 255) / 256, 256>>>(ei);

    for (int i = 0; i < 3; i++) {
        if (i > 0) {
            Job j0 = {wcp + (1 + i) * WSTRIDE, bl + (size_t)i * DD, xlp};
            Job j1 = {wcp + (4 + i) * WSTRIDE, nullptr, xrp};
            Job j2 = {wcp + (7 + (i - 1)) * WSTRIDE, bres + (size_t)(i - 1) * DD, resp};
            gemm_mma_k<<<GX, 512, GEMM_SMEM>>>(hp, j0, j1, j2, 3, NN);
        }

        agg_k<<<NN / 8, 256>>>(xlp, xrp, att + (size_t)i * DD, b_out + (size_t)i * DD);

        colsum_part_k<<<CPB, 128>>>();
        colsum_fin_k<<<1, 128>>>();

        const float* rsrc = (i > 0) ? resp : hp;
        float* dst = (i == 2) ? out : hp;
        epilogue_k<<<NN / 8, 256>>>(rsrc, ln_g + (size_t)i * DD, ln_b + (size_t)i * DD,
                                    dst, (i < 2) ? 1 : 0);
    }
}

// round 13
// speedup vs baseline: 1.1114x; 1.1114x over previous
#include <cuda_runtime.h>
#include <cuda_bf16.h>
#include <cstdint>
#include <cstddef>

#define NN 100000
#define EE 800000
#define DD 128
#define AGG_BLOCKS (NN / 8)   // 12500, exact

// ---------------- scratch (device globals; no allocation allowed) -------------
__device__ float g_h[NN * DD];
__device__ float g_xl[NN * DD];
__device__ float g_xr[NN * DD];
__device__ float g_res[NN * DD];
__device__ float g_agg[NN * DD];
__device__ int   g_deg[NN];
__device__ int   g_rowptr[NN + 1];
__device__ int   g_cursor[NN];
__device__ int   g_csrc[EE];
__device__ int   g_blocksums[256];
__device__ int   g_blockoff[256];
__device__ float g_colpart[AGG_BLOCKS * DD];   // per-agg-block column partials
__device__ float g_colmid[125 * DD];
__device__ float g_colmean[DD];

// preconverted weights: 9 matrices x (hi,lo) x [128 rows x 136 bf16] padded image
#define LDSB 136
#define RSB  (LDSB * 2)                 // 272 bytes per row
#define BTILE_B (128 * RSB)             // 34816 bytes per B tile
#define WIMG_ELEMS (128 * LDSB)         // 17408 bf16 per tile
__device__ __nv_bfloat16 g_wconv[9 * 2 * WIMG_ELEMS];

// ---------------- CSR build ---------------------------------------------------
__global__ void zero_deg_k() {
    int i = blockIdx.x * blockDim.x + threadIdx.x;
    if (i < NN) g_deg[i] = 0;
}
__global__ void hist_k(const int* __restrict__ ei) {
    int e = blockIdx.x * blockDim.x + threadIdx.x;
    if (e < EE) atomicAdd(&g_deg[ei[EE + e]], 1);
}

#define SC 512
#define SB ((NN + SC - 1) / SC)   // 196

__global__ void scan1_k() {
    __shared__ int s[SC];
    int b = blockIdx.x, t = threadIdx.x;
    int i = b * SC + t;
    int v = (i < NN) ? g_deg[i] : 0;
    s[t] = v;
    __syncthreads();
    for (int off = 1; off < SC; off <<= 1) {
        int x = (t >= off) ? s[t - off] : 0;
        __syncthreads();
        s[t] += x;
        __syncthreads();
    }
    if (i < NN) g_rowptr[i] = s[t] - v;
    if (t == SC - 1) g_blocksums[b] = s[t];
}

__global__ void scan2_k() {
    __shared__ int s[256];
    int t = threadIdx.x;
    int v = (t < SB) ? g_blocksums[t] : 0;
    s[t] = v;
    __syncthreads();
    for (int off = 1; off < 256; off <<= 1) {
        int x = (t >= off) ? s[t - off] : 0;
        __syncthreads();
        s[t] += x;
        __syncthreads();
    }
    if (t < SB) g_blockoff[t] = s[t] - v;
    if (t == 255) g_rowptr[NN] = s[255];
}

__global__ void scan3_k() {
    int b = blockIdx.x, t = threadIdx.x;
    int i = b * SC + t;
    if (i < NN) {
        int v = g_rowptr[i] + g_blockoff[b];
        g_rowptr[i] = v;
        g_cursor[i] = v;
    }
}

__global__ void scatter_k(const int* __restrict__ ei) {
    int e = blockIdx.x * blockDim.x + threadIdx.x;
    if (e < EE) {
        int s = ei[e];
        int d = ei[EE + e];
        int pos = atomicAdd(&g_cursor[d], 1);
        g_csrc[pos] = s;
    }
}

// ---------------- helpers ------------------------------------------------------
__device__ __forceinline__ uint32_t smem_u32(const void* p) {
    uint32_t a;
    asm("{ .reg .u64 t; cvta.to.shared.u64 t, %1; cvt.u32.u64 %0, t; }" : "=r"(a) : "l"(p));
    return a;
}

__device__ __forceinline__ void ldm_x4(uint32_t* r, uint32_t addr) {
    asm volatile("ldmatrix.sync.aligned.m8n8.x4.shared.b16 {%0,%1,%2,%3}, [%4];"
                 : "=r"(r[0]), "=r"(r[1]), "=r"(r[2]), "=r"(r[3]) : "r"(addr));
}

__device__ __forceinline__ void mma16816(float* c, const uint32_t* a, uint32_t b0, uint32_t b1) {
    asm volatile(
        "mma.sync.aligned.m16n8k16.row.col.f32.bf16.bf16.f32 "
        "{%0,%1,%2,%3}, {%4,%5,%6,%7}, {%8,%9}, {%0,%1,%2,%3};"
        : "+f"(c[0]), "+f"(c[1]), "+f"(c[2]), "+f"(c[3])
        : "r"(a[0]), "r"(a[1]), "r"(a[2]), "r"(a[3]), "r"(b0), "r"(b1));
}

__device__ __forceinline__ void split8(const float* v, uint4& hi, uint4& lo) {
    uint32_t h[4], l[4];
    #pragma unroll
    for (int p = 0; p < 4; p++) {
        float a = v[2 * p], b = v[2 * p + 1];
        __nv_bfloat16 ha = __float2bfloat16_rn(a), hb = __float2bfloat16_rn(b);
        float ra = a - __bfloat162float(ha), rb = b - __bfloat162float(hb);
        __nv_bfloat16 la = __float2bfloat16_rn(ra);
        __nv_bfloat16 lb = __float2bfloat16_rn(rb);
        h[p] = ((uint32_t)__bfloat16_as_ushort(hb) << 16) | __bfloat16_as_ushort(ha);
        l[p] = ((uint32_t)__bfloat16_as_ushort(lb) << 16) | __bfloat16_as_ushort(la);
    }
    hi = make_uint4(h[0], h[1], h[2], h[3]);
    lo = make_uint4(l[0], l[1], l[2], l[3]);
}

// ---------------- W pre-conversion: 9 matrices -> padded transposed bf16 image -
__global__ void wconv_k(const float* __restrict__ w0, const float* __restrict__ wl,
                        const float* __restrict__ wr, const float* __restrict__ wres) {
    int mat = blockIdx.x;   // 0: w_in, 1..3: Wl, 4..6: Wr, 7..8: Wres
    const float* W;
    if (mat == 0)      W = w0;
    else if (mat <= 3) W = wl + (size_t)(mat - 1) * DD * DD;
    else if (mat <= 6) W = wr + (size_t)(mat - 4) * DD * DD;
    else               W = wres + (size_t)(mat - 7) * DD * DD;

    __nv_bfloat16* hiT = g_wconv + (size_t)mat * 2 * WIMG_ELEMS;
    __nv_bfloat16* loT = hiT + WIMG_ELEMS;
    int tid = threadIdx.x;
    #pragma unroll
    for (int it = 0; it < 8; it++) {
        int t = tid + it * 256;       // 0..2047
        int n = t & 127, c = t >> 7;  // col n, 8-wide k chunk
        int k0 = c * 8;
        float v[8];
        #pragma unroll
        for (int q = 0; q < 8; q++) v[q] = W[(size_t)(k0 + q) * 128 + n];
        uint4 hi, lo;
        split8(v, hi, lo);
        size_t off = (size_t)n * LDSB + k0;
        *(uint4*)(hiT + off) = hi;
        *(uint4*)(loT + off) = lo;
    }
}

// ---------------- HMMA GEMM: C[M,128] = A[M,128] @ W[128,128] (+bias) ---------
// bf16 hi/lo split, 3 compensated products, fp32 accumulators (mma.sync).
// 256-row A tile @ 512 threads; W tiles copied preconverted.
struct Job { const __nv_bfloat16* Wc; const float* bias; float* out; };

#define RT 256                          // A tile rows
#define ATILE_B (RT * RSB)              // 69632 bytes per A tile (hi or lo)
#define OFF_AHI 0
#define OFF_ALO ATILE_B
#define OFF_BHI (2 * ATILE_B)
#define OFF_BLO (2 * ATILE_B + BTILE_B)
#define GEMM_SMEM (2 * ATILE_B + 2 * BTILE_B)   // 208896 bytes

__global__ void __launch_bounds__(512, 1)
gemm_mma_k(const float* __restrict__ A, Job j0, Job j1, Job j2, int njobs, int M) {
    extern __shared__ char sm[];
    uint32_t smb = smem_u32(sm);
    int tid = threadIdx.x;
    int wid = tid >> 5;
    int lane = tid & 31;
    int rowBase = blockIdx.x * RT;

    // ---- load & split A tile [256 x 128] fp32 -> bf16 hi/lo (once) ----
    #pragma unroll
    for (int it = 0; it < 8; it++) {
        int t = tid + it * 512;       // 0..4095
        int r = t >> 4, c = t & 15;
        int k0 = c * 8;
        float v[8];
        int gr = rowBase + r;
        if (gr < M) {
            *(float4*)(v)     = *(const float4*)(A + (size_t)gr * 128 + k0);
            *(float4*)(v + 4) = *(const float4*)(A + (size_t)gr * 128 + k0 + 4);
        } else {
            #pragma unroll
            for (int q = 0; q < 8; q++) v[q] = 0.f;
        }
        uint4 hi, lo;
        split8(v, hi, lo);
        uint32_t off = (uint32_t)r * RSB + (uint32_t)k0 * 2;
        *(uint4*)(sm + OFF_AHI + off) = hi;
        *(uint4*)(sm + OFF_ALO + off) = lo;
    }

    // warp tiling: 8x2 warps, each 32 rows x 64 cols
    int rm = (wid & 7) * 32;
    int cn = (wid >> 3) * 64;

    // lane-derived ldmatrix source offsets
    int la16 = lane & 15;
    int akoff = (lane >> 4) * 8;
    int bq = lane >> 3;
    int br = lane & 7;
    int brow_add = (bq >> 1) * 8 + br;
    int bkoff = (bq & 1) * 8;
    int g = lane >> 2, tq = lane & 3;

    for (int jj = 0; jj < njobs; jj++) {
        Job jb = (jj == 0) ? j0 : (jj == 1 ? j1 : j2);

        if (jj > 0) __syncthreads();   // previous job's B reads complete

        // ---- copy preconverted W image (hi+lo = 69632 B = 4352 uint4) ----
        {
            const uint4* src = (const uint4*)jb.Wc;      // hi tile then lo tile, contiguous
            uint4* dst = (uint4*)(sm + OFF_BHI);
            for (int idx = tid; idx < 4352; idx += 512)
                dst[idx] = src[idx];
        }
        __syncthreads();

        float acc[2][8][4];
        #pragma unroll
        for (int mt = 0; mt < 2; mt++)
            #pragma unroll
            for (int nt = 0; nt < 8; nt++)
                #pragma unroll
                for (int q = 0; q < 4; q++) acc[mt][nt][q] = 0.f;

        #pragma unroll
        for (int kk = 0; kk < 8; kk++) {
            int k0 = kk * 16;
            uint32_t Ah[2][4], Al[2][4];
            #pragma unroll
            for (int mt = 0; mt < 2; mt++) {
                uint32_t aoff = (uint32_t)(rm + mt * 16 + la16) * RSB + (uint32_t)(k0 + akoff) * 2;
                ldm_x4(Ah[mt], smb + OFF_AHI + aoff);
                ldm_x4(Al[mt], smb + OFF_ALO + aoff);
            }
            uint32_t Bh[4][4], Bl[4][4];
            #pragma unroll
            for (int nt2 = 0; nt2 < 4; nt2++) {
                uint32_t boff = (uint32_t)(cn + nt2 * 16 + brow_add) * RSB + (uint32_t)(k0 + bkoff) * 2;
                ldm_x4(Bh[nt2], smb + OFF_BHI + boff);
                ldm_x4(Bl[nt2], smb + OFF_BLO + boff);
            }
            #pragma unroll
            for (int mt = 0; mt < 2; mt++) {
                #pragma unroll
                for (int nt = 0; nt < 8; nt++) {
                    int nt2 = nt >> 1, hh = (nt & 1) * 2;
                    mma16816(acc[mt][nt], Ah[mt], Bh[nt2][hh], Bh[nt2][hh + 1]);
                    mma16816(acc[mt][nt], Ah[mt], Bl[nt2][hh], Bl[nt2][hh + 1]);
                    mma16816(acc[mt][nt], Al[mt], Bh[nt2][hh], Bh[nt2][hh + 1]);
                }
            }
        }

        // ---- epilogue: accumulator layout -> global (+bias) ----
        #pragma unroll
        for (int mt = 0; mt < 2; mt++) {
            int r0 = rowBase + rm + mt * 16 + g;
            int r1 = r0 + 8;
            #pragma unroll
            for (int nt = 0; nt < 8; nt++) {
                int col = cn + nt * 8 + 2 * tq;
                float bx = 0.f, by = 0.f;
                if (jb.bias) { bx = jb.bias[col]; by = jb.bias[col + 1]; }
                if (r0 < M) {
                    float2 o = {acc[mt][nt][0] + bx, acc[mt][nt][1] + by};
                    *(float2*)(jb.out + (size_t)r0 * 128 + col) = o;
                }
                if (r1 < M) {
                    float2 o = {acc[mt][nt][2] + bx, acc[mt][nt][3] + by};
                    *(float2*)(jb.out + (size_t)r1 * 128 + col) = o;
                }
            }
        }
    }
}

// ---------------- per-dst softmax aggregation (one warp per node) -------------
// Plain exp (logits provably tiny), 2-wide edge unroll (R11 config).
// Fused: per-block column partial sums of the aggregated output (deterministic
// smem tree) -> g_colpart, replacing the 51MB colsum_part re-read.
__global__ void agg_k(const float* __restrict__ xl, const float* __restrict__ xr,
                      const float* __restrict__ att, const float* __restrict__ bout) {
    __shared__ float sred[8][128];
    int tid = threadIdx.x;
    int wid = tid >> 5;
    int lane = tid & 31;
    int warp = blockIdx.x * 8 + wid;    // NN divisible by 8: always < NN

    const float4 xrv = *(const float4*)(xr + (size_t)warp * 128 + lane * 4);
    const float4 av  = *(const float4*)(att + lane * 4);

    float a0 = 0.f, a1 = 0.f, a2 = 0.f, a3 = 0.f, s = 0.f;

    int beg = g_rowptr[warp];
    int n = g_rowptr[warp + 1] - beg;
    const int* csrc = g_csrc + beg;

    float4 b0, b1;
    if (n > 0) b0 = *(const float4*)(xl + (size_t)csrc[0] * 128 + lane * 4);
    if (n > 1) b1 = *(const float4*)(xl + (size_t)csrc[1] * 128 + lane * 4);

    for (int j = 0; j < n; j += 2) {
        float4 c0 = b0, c1 = b1;
        bool has1 = (j + 1 < n);
        if (j + 2 < n) b0 = *(const float4*)(xl + (size_t)csrc[j + 2] * 128 + lane * 4);
        if (j + 3 < n) b1 = *(const float4*)(xl + (size_t)csrc[j + 3] * 128 + lane * 4);

        float u0 = c0.x + xrv.x; u0 = fmaxf(u0, 0.2f * u0);
        float u1 = c0.y + xrv.y; u1 = fmaxf(u1, 0.2f * u1);
        float u2 = c0.z + xrv.z; u2 = fmaxf(u2, 0.2f * u2);
        float u3 = c0.w + xrv.w; u3 = fmaxf(u3, 0.2f * u3);
        float p0 = u0 * av.x + u1 * av.y + u2 * av.z + u3 * av.w;
        float w0 = c1.x + xrv.x; w0 = fmaxf(w0, 0.2f * w0);
        float w1 = c1.y + xrv.y; w1 = fmaxf(w1, 0.2f * w1);
        float w2 = c1.z + xrv.z; w2 = fmaxf(w2, 0.2f * w2);
        float w3 = c1.w + xrv.w; w3 = fmaxf(w3, 0.2f * w3);
        float p1 = w0 * av.x + w1 * av.y + w2 * av.z + w3 * av.w;

        p0 += __shfl_xor_sync(0xffffffffu, p0, 1);
        p1 += __shfl_xor_sync(0xffffffffu, p1, 1);
        p0 += __shfl_xor_sync(0xffffffffu, p0, 2);
        p1 += __shfl_xor_sync(0xffffffffu, p1, 2);
        p0 += __shfl_xor_sync(0xffffffffu, p0, 4);
        p1 += __shfl_xor_sync(0xffffffffu, p1, 4);

        float e0 = __expf(p0);
        float e1 = has1 ? __expf(p1) : 0.f;

        s  += e0 + e1;
        a0 += e0 * c0.x;
        a1 += e0 * c0.y;
        a2 += e0 * c0.z;
        a3 += e0 * c0.w;
        if (has1) {
            a0 += e1 * c1.x;
            a1 += e1 * c1.y;
            a2 += e1 * c1.z;
            a3 += e1 * c1.w;
        }
    }

    float inv = 1.f / (s + 1e-16f);
    float4 bo = *(const float4*)(bout + lane * 4);
    float4 o;
    o.x = a0 * inv + bo.x;
    o.y = a1 * inv + bo.y;
    o.z = a2 * inv + bo.z;
    o.w = a3 * inv + bo.w;
    *(float4*)(g_agg + (size_t)warp * 128 + lane * 4) = o;

    // fused per-block column partial (deterministic fixed-order tree)
    *(float4*)(&sred[wid][lane * 4]) = o;
    __syncthreads();
    if (tid < 128) {
        float t = 0.f;
        #pragma unroll
        for (int w = 0; w < 8; w++) t += sred[w][tid];
        g_colpart[(size_t)blockIdx.x * 128 + tid] = t;
    }
}

// ---------------- column mean reduction: 12500 partials -> 125 -> mean --------
__global__ void colsum_mid_k() {
    int c = threadIdx.x;           // 128 threads
    int b = blockIdx.x;            // 125 blocks
    float s0 = 0.f, s1 = 0.f, s2 = 0.f, s3 = 0.f;
    // rows b, b+125, ..., total 100 rows
    int r = b;
    for (; r + 3 * 125 < AGG_BLOCKS; r += 4 * 125) {
        s0 += g_colpart[(size_t)r * 128 + c];
        s1 += g_colpart[(size_t)(r + 125) * 128 + c];
        s2 += g_colpart[(size_t)(r + 250) * 128 + c];
        s3 += g_colpart[(size_t)(r + 375) * 128 + c];
    }
    for (; r < AGG_BLOCKS; r += 125) s0 += g_colpart[(size_t)r * 128 + c];
    g_colmid[b * 128 + c] = (s0 + s1) + (s2 + s3);
}
__global__ void colsum_fin_k() {
    int c = threadIdx.x;
    float s = 0.f;
    for (int b = 0; b < 125; b++) s += g_colmid[b * 128 + c];
    g_colmean[c] = s * (1.0f / NN);
}

// ---------------- fused pairnorm + residual + layernorm + relu ----------------
__global__ void epilogue_k(const float* __restrict__ res,
                           const float* __restrict__ lng, const float* __restrict__ lnb,
                           float* __restrict__ out, int relu) {
    int warp = (blockIdx.x * blockDim.x + threadIdx.x) >> 5;
    int lane = threadIdx.x & 31;
    if (warp >= NN) return;

    float4 a4 = *(const float4*)(g_agg + (size_t)warp * 128 + lane * 4);
    float4 cm = *(const float4*)(g_colmean + lane * 4);
    float x0 = a4.x - cm.x, x1 = a4.y - cm.y, x2 = a4.z - cm.z, x3 = a4.w - cm.w;

    float ss = x0 * x0 + x1 * x1 + x2 * x2 + x3 * x3;
    #pragma unroll
    for (int off = 16; off > 0; off >>= 1) ss += __shfl_xor_sync(0xffffffffu, ss, off);
    float l2 = sqrtf(ss) + 1e-6f;
    float sc = 316.2277660168379f / l2;

    float4 r4 = *(const float4*)(res + (size_t)warp * 128 + lane * 4);
    float h0 = x0 * sc + r4.x;
    float h1 = x1 * sc + r4.y;
    float h2 = x2 * sc + r4.z;
    float h3 = x3 * sc + r4.w;

    float sm = h0 + h1 + h2 + h3;
    #pragma unroll
    for (int off = 16; off > 0; off >>= 1) sm += __shfl_xor_sync(0xffffffffu, sm, off);
    float mu = sm * (1.0f / 128.0f);

    float d0 = h0 - mu, d1 = h1 - mu, d2 = h2 - mu, d3 = h3 - mu;
    float sv = d0 * d0 + d1 * d1 + d2 * d2 + d3 * d3;
    #pragma unroll
    for (int off = 16; off > 0; off >>= 1) sv += __shfl_xor_sync(0xffffffffu, sv, off);
    float rs = rsqrtf(sv * (1.0f / 128.0f) + 1e-5f);

    float4 g4 = *(const float4*)(lng + lane * 4);
    float4 b4 = *(const float4*)(lnb + lane * 4);
    float y0 = d0 * rs * g4.x + b4.x;
    float y1 = d1 * rs * g4.y + b4.y;
    float y2 = d2 * rs * g4.z + b4.z;
    float y3 = d3 * rs * g4.w + b4.w;
    if (relu) {
        y0 = fmaxf(y0, 0.f); y1 = fmaxf(y1, 0.f);
        y2 = fmaxf(y2, 0.f); y3 = fmaxf(y3, 0.f);
    }
    float4 o = {y0, y1, y2, y3};
    *(float4*)(out + (size_t)warp * 128 + lane * 4) = o;
}

// ---------------- host orchestration ------------------------------------------
extern "C" void kernel_launch(void* const* d_in, const int* in_sizes, int n_in,
                              void* d_out, int out_size) {
    const float* x     = (const float*)d_in[0];
    const int*   ei    = (const int*)  d_in[1];
    const float* w_in  = (const float*)d_in[2];
    const float* b_in  = (const float*)d_in[3];
    const float* Wl    = (const float*)d_in[4];
    const float* bl    = (const float*)d_in[5];
    const float* Wr    = (const float*)d_in[6];
    const float* att   = (const float*)d_in[7];
    const float* b_out = (const float*)d_in[8];
    const float* Wres  = (const float*)d_in[9];
    const float* bres  = (const float*)d_in[10];
    const float* ln_g  = (const float*)d_in[11];
    const float* ln_b  = (const float*)d_in[12];
    float* out = (float*)d_out;

    cudaFuncSetAttribute(gemm_mma_k, cudaFuncAttributeMaxDynamicSharedMemorySize, GEMM_SMEM);

    float *hp, *xlp, *xrp, *resp;
    cudaGetSymbolAddress((void**)&hp,   g_h);
    cudaGetSymbolAddress((void**)&xlp,  g_xl);
    cudaGetSymbolAddress((void**)&xrp,  g_xr);
    cudaGetSymbolAddress((void**)&resp, g_res);
    __nv_bfloat16* wcp;
    cudaGetSymbolAddress((void**)&wcp, g_wconv);

    const int GX = (NN + RT - 1) / RT;
    const size_t WSTRIDE = 2 * WIMG_ELEMS;

    wconv_k<<<9, 256>>>(w_in, Wl, Wr, Wres);
    zero_deg_k<<<(NN + 255) / 256, 256>>>();

    // input projection: h = x @ w_in + b_in
    {
        Job j0 = {wcp, b_in, hp};
        gemm_mma_k<<<GX, 512, GEMM_SMEM>>>(x, j0, j0, j0, 1, NN);
    }
    // layer-0 GEMM (Wl, Wr)
    {
        Job j0 = {wcp + 1 * WSTRIDE, bl, xlp};
        Job j1 = {wcp + 4 * WSTRIDE, nullptr, xrp};
        gemm_mma_k<<<GX, 512, GEMM_SMEM>>>(hp, j0, j1, j1, 2, NN);
    }

    // CSR build (needed before agg)
    hist_k<<<(EE + 255) / 256, 256>>>(ei);
    scan1_k<<<SB, SC>>>();
    scan2_k<<<1, 256>>>();
    scan3_k<<<SB, SC>>>();
    scatter_k<<<(EE + 255) / 256, 256>>>(ei);

    for (int i = 0; i < 3; i++) {
        if (i > 0) {
            Job j0 = {wcp + (1 + i) * WSTRIDE, bl + (size_t)i * DD, xlp};
            Job j1 = {wcp + (4 + i) * WSTRIDE, nullptr, xrp};
            Job j2 = {wcp + (7 + (i - 1)) * WSTRIDE, bres + (size_t)(i - 1) * DD, resp};
            gemm_mma_k<<<GX, 512, GEMM_SMEM>>>(hp, j0, j1, j2, 3, NN);
        }

        agg_k<<<AGG_BLOCKS, 256>>>(xlp, xrp, att + (size_t)i * DD, b_out + (size_t)i * DD);

        colsum_mid_k<<<125, 128>>>();
        colsum_fin_k<<<1, 128>>>();

        const float* rsrc = (i > 0) ? resp : hp;
        float* dst = (i == 2) ? out : hp;
        epilogue_k<<<NN / 8, 256>>>(rsrc, ln_g + (size_t)i * DD, ln_b + (size_t)i * DD,
                                    dst, (i < 2) ? 1 : 0);
    }
}

// round 14
// speedup vs baseline: 1.1279x; 1.0148x over previous
#include <cuda_runtime.h>
#include <cuda_bf16.h>
#include <cstdint>
#include <cstddef>

#define NN 100000
#define EE 800000
#define DD 128
#define AGG_BLOCKS (NN / 8)   // 12500, exact

// ---------------- scratch (device globals; no allocation allowed) -------------
__device__ float g_h[NN * DD];
__device__ float g_xl[NN * DD];
__device__ float g_xr[NN * DD];
__device__ float g_res[NN * DD];
__device__ float g_agg[NN * DD];
__device__ int   g_deg[NN];
__device__ int   g_rowptr[NN + 1];
__device__ int   g_cursor[NN];
__device__ int   g_csrc[EE];
__device__ int   g_blocksums[256];
__device__ int   g_blockoff[256];
__device__ float g_colpart[AGG_BLOCKS * DD];   // per-agg-block column partials
__device__ float g_colmid[125 * DD];
__device__ float g_colmean[DD];

// preconverted weights: 9 matrices x (hi,lo) x [128 rows x 136 bf16] padded image
#define LDSB 136
#define RSB  (LDSB * 2)                 // 272 bytes per row
#define BTILE_B (128 * RSB)             // 34816 bytes per B tile
#define WIMG_ELEMS (128 * LDSB)         // 17408 bf16 per tile
__device__ __nv_bfloat16 g_wconv[9 * 2 * WIMG_ELEMS];

// ---------------- CSR build ---------------------------------------------------
__global__ void zero_deg_k() {
    int i = blockIdx.x * blockDim.x + threadIdx.x;
    if (i < NN) g_deg[i] = 0;
}
__global__ void hist_k(const int* __restrict__ ei) {
    int e = blockIdx.x * blockDim.x + threadIdx.x;
    if (e < EE) atomicAdd(&g_deg[ei[EE + e]], 1);
}

#define SC 512
#define SB ((NN + SC - 1) / SC)   // 196

__global__ void scan1_k() {
    __shared__ int s[SC];
    int b = blockIdx.x, t = threadIdx.x;
    int i = b * SC + t;
    int v = (i < NN) ? g_deg[i] : 0;
    s[t] = v;
    __syncthreads();
    for (int off = 1; off < SC; off <<= 1) {
        int x = (t >= off) ? s[t - off] : 0;
        __syncthreads();
        s[t] += x;
        __syncthreads();
    }
    if (i < NN) g_rowptr[i] = s[t] - v;
    if (t == SC - 1) g_blocksums[b] = s[t];
}

__global__ void scan2_k() {
    __shared__ int s[256];
    int t = threadIdx.x;
    int v = (t < SB) ? g_blocksums[t] : 0;
    s[t] = v;
    __syncthreads();
    for (int off = 1; off < 256; off <<= 1) {
        int x = (t >= off) ? s[t - off] : 0;
        __syncthreads();
        s[t] += x;
        __syncthreads();
    }
    if (t < SB) g_blockoff[t] = s[t] - v;
    if (t == 255) g_rowptr[NN] = s[255];
}

__global__ void scan3_k() {
    int b = blockIdx.x, t = threadIdx.x;
    int i = b * SC + t;
    if (i < NN) {
        int v = g_rowptr[i] + g_blockoff[b];
        g_rowptr[i] = v;
        g_cursor[i] = v;
    }
}

__global__ void scatter_k(const int* __restrict__ ei) {
    int e = blockIdx.x * blockDim.x + threadIdx.x;
    if (e < EE) {
        int s = ei[e];
        int d = ei[EE + e];
        int pos = atomicAdd(&g_cursor[d], 1);
        g_csrc[pos] = s;
    }
}

// ---------------- helpers ------------------------------------------------------
__device__ __forceinline__ uint32_t smem_u32(const void* p) {
    uint32_t a;
    asm("{ .reg .u64 t; cvta.to.shared.u64 t, %1; cvt.u32.u64 %0, t; }" : "=r"(a) : "l"(p));
    return a;
}

__device__ __forceinline__ void ldm_x4(uint32_t* r, uint32_t addr) {
    asm volatile("ldmatrix.sync.aligned.m8n8.x4.shared.b16 {%0,%1,%2,%3}, [%4];"
                 : "=r"(r[0]), "=r"(r[1]), "=r"(r[2]), "=r"(r[3]) : "r"(addr));
}

__device__ __forceinline__ void mma16816(float* c, const uint32_t* a, uint32_t b0, uint32_t b1) {
    asm volatile(
        "mma.sync.aligned.m16n8k16.row.col.f32.bf16.bf16.f32 "
        "{%0,%1,%2,%3}, {%4,%5,%6,%7}, {%8,%9}, {%0,%1,%2,%3};"
        : "+f"(c[0]), "+f"(c[1]), "+f"(c[2]), "+f"(c[3])
        : "r"(a[0]), "r"(a[1]), "r"(a[2]), "r"(a[3]), "r"(b0), "r"(b1));
}

__device__ __forceinline__ void split8(const float* v, uint4& hi, uint4& lo) {
    uint32_t h[4], l[4];
    #pragma unroll
    for (int p = 0; p < 4; p++) {
        float a = v[2 * p], b = v[2 * p + 1];
        __nv_bfloat16 ha = __float2bfloat16_rn(a), hb = __float2bfloat16_rn(b);
        float ra = a - __bfloat162float(ha), rb = b - __bfloat162float(hb);
        __nv_bfloat16 la = __float2bfloat16_rn(ra);
        __nv_bfloat16 lb = __float2bfloat16_rn(rb);
        h[p] = ((uint32_t)__bfloat16_as_ushort(hb) << 16) | __bfloat16_as_ushort(ha);
        l[p] = ((uint32_t)__bfloat16_as_ushort(lb) << 16) | __bfloat16_as_ushort(la);
    }
    hi = make_uint4(h[0], h[1], h[2], h[3]);
    lo = make_uint4(l[0], l[1], l[2], l[3]);
}

// ---------------- W pre-conversion: 9 matrices -> padded transposed bf16 image -
__global__ void wconv_k(const float* __restrict__ w0, const float* __restrict__ wl,
                        const float* __restrict__ wr, const float* __restrict__ wres) {
    int mat = blockIdx.x;   // 0: w_in, 1..3: Wl, 4..6: Wr, 7..8: Wres
    const float* W;
    if (mat == 0)      W = w0;
    else if (mat <= 3) W = wl + (size_t)(mat - 1) * DD * DD;
    else if (mat <= 6) W = wr + (size_t)(mat - 4) * DD * DD;
    else               W = wres + (size_t)(mat - 7) * DD * DD;

    __nv_bfloat16* hiT = g_wconv + (size_t)mat * 2 * WIMG_ELEMS;
    __nv_bfloat16* loT = hiT + WIMG_ELEMS;
    int tid = threadIdx.x;
    #pragma unroll
    for (int it = 0; it < 8; it++) {
        int t = tid + it * 256;       // 0..2047
        int n = t & 127, c = t >> 7;  // col n, 8-wide k chunk
        int k0 = c * 8;
        float v[8];
        #pragma unroll
        for (int q = 0; q < 8; q++) v[q] = W[(size_t)(k0 + q) * 128 + n];
        uint4 hi, lo;
        split8(v, hi, lo);
        size_t off = (size_t)n * LDSB + k0;
        *(uint4*)(hiT + off) = hi;
        *(uint4*)(loT + off) = lo;
    }
}

// ---------------- HMMA GEMM: C[M,128] = A[M,128] @ W[128,128] (+bias) ---------
// bf16 hi/lo split, 3 compensated products, fp32 accumulators (mma.sync).
// 256-row A tile @ 512 threads; W tiles copied preconverted.
struct Job { const __nv_bfloat16* Wc; const float* bias; float* out; };

#define RT 256                          // A tile rows
#define ATILE_B (RT * RSB)              // 69632 bytes per A tile (hi or lo)
#define OFF_AHI 0
#define OFF_ALO ATILE_B
#define OFF_BHI (2 * ATILE_B)
#define OFF_BLO (2 * ATILE_B + BTILE_B)
#define GEMM_SMEM (2 * ATILE_B + 2 * BTILE_B)   // 208896 bytes

__global__ void __launch_bounds__(512, 1)
gemm_mma_k(const float* __restrict__ A, Job j0, Job j1, Job j2, int njobs, int M) {
    extern __shared__ char sm[];
    uint32_t smb = smem_u32(sm);
    int tid = threadIdx.x;
    int wid = tid >> 5;
    int lane = tid & 31;
    int rowBase = blockIdx.x * RT;

    // ---- load & split A tile [256 x 128] fp32 -> bf16 hi/lo (once) ----
    #pragma unroll
    for (int it = 0; it < 8; it++) {
        int t = tid + it * 512;       // 0..4095
        int r = t >> 4, c = t & 15;
        int k0 = c * 8;
        float v[8];
        int gr = rowBase + r;
        if (gr < M) {
            *(float4*)(v)     = *(const float4*)(A + (size_t)gr * 128 + k0);
            *(float4*)(v + 4) = *(const float4*)(A + (size_t)gr * 128 + k0 + 4);
        } else {
            #pragma unroll
            for (int q = 0; q < 8; q++) v[q] = 0.f;
        }
        uint4 hi, lo;
        split8(v, hi, lo);
        uint32_t off = (uint32_t)r * RSB + (uint32_t)k0 * 2;
        *(uint4*)(sm + OFF_AHI + off) = hi;
        *(uint4*)(sm + OFF_ALO + off) = lo;
    }

    // warp tiling: 8x2 warps, each 32 rows x 64 cols
    int rm = (wid & 7) * 32;
    int cn = (wid >> 3) * 64;

    // lane-derived ldmatrix source offsets
    int la16 = lane & 15;
    int akoff = (lane >> 4) * 8;
    int bq = lane >> 3;
    int br = lane & 7;
    int brow_add = (bq >> 1) * 8 + br;
    int bkoff = (bq & 1) * 8;
    int g = lane >> 2, tq = lane & 3;

    for (int jj = 0; jj < njobs; jj++) {
        Job jb = (jj == 0) ? j0 : (jj == 1 ? j1 : j2);

        if (jj > 0) __syncthreads();   // previous job's B reads complete

        // ---- copy preconverted W image (hi+lo = 69632 B = 4352 uint4) ----
        {
            const uint4* src = (const uint4*)jb.Wc;      // hi tile then lo tile, contiguous
            uint4* dst = (uint4*)(sm + OFF_BHI);
            for (int idx = tid; idx < 4352; idx += 512)
                dst[idx] = src[idx];
        }
        __syncthreads();

        float acc[2][8][4];
        #pragma unroll
        for (int mt = 0; mt < 2; mt++)
            #pragma unroll
            for (int nt = 0; nt < 8; nt++)
                #pragma unroll
                for (int q = 0; q < 4; q++) acc[mt][nt][q] = 0.f;

        #pragma unroll
        for (int kk = 0; kk < 8; kk++) {
            int k0 = kk * 16;
            uint32_t Ah[2][4], Al[2][4];
            #pragma unroll
            for (int mt = 0; mt < 2; mt++) {
                uint32_t aoff = (uint32_t)(rm + mt * 16 + la16) * RSB + (uint32_t)(k0 + akoff) * 2;
                ldm_x4(Ah[mt], smb + OFF_AHI + aoff);
                ldm_x4(Al[mt], smb + OFF_ALO + aoff);
            }
            uint32_t Bh[4][4], Bl[4][4];
            #pragma unroll
            for (int nt2 = 0; nt2 < 4; nt2++) {
                uint32_t boff = (uint32_t)(cn + nt2 * 16 + brow_add) * RSB + (uint32_t)(k0 + bkoff) * 2;
                ldm_x4(Bh[nt2], smb + OFF_BHI + boff);
                ldm_x4(Bl[nt2], smb + OFF_BLO + boff);
            }
            #pragma unroll
            for (int mt = 0; mt < 2; mt++) {
                #pragma unroll
                for (int nt = 0; nt < 8; nt++) {
                    int nt2 = nt >> 1, hh = (nt & 1) * 2;
                    mma16816(acc[mt][nt], Ah[mt], Bh[nt2][hh], Bh[nt2][hh + 1]);
                    mma16816(acc[mt][nt], Ah[mt], Bl[nt2][hh], Bl[nt2][hh + 1]);
                    mma16816(acc[mt][nt], Al[mt], Bh[nt2][hh], Bh[nt2][hh + 1]);
                }
            }
        }

        // ---- epilogue: accumulator layout -> global (+bias) ----
        #pragma unroll
        for (int mt = 0; mt < 2; mt++) {
            int r0 = rowBase + rm + mt * 16 + g;
            int r1 = r0 + 8;
            #pragma unroll
            for (int nt = 0; nt < 8; nt++) {
                int col = cn + nt * 8 + 2 * tq;
                float bx = 0.f, by = 0.f;
                if (jb.bias) { bx = jb.bias[col]; by = jb.bias[col + 1]; }
                if (r0 < M) {
                    float2 o = {acc[mt][nt][0] + bx, acc[mt][nt][1] + by};
                    *(float2*)(jb.out + (size_t)r0 * 128 + col) = o;
                }
                if (r1 < M) {
                    float2 o = {acc[mt][nt][2] + bx, acc[mt][nt][3] + by};
                    *(float2*)(jb.out + (size_t)r1 * 128 + col) = o;
                }
            }
        }
    }
}

// ---------------- per-dst softmax aggregation (one warp per node) -------------
// Plain exp (logits provably tiny), 2-wide edge unroll, fused column partials.
__global__ void agg_k(const float* __restrict__ xl, const float* __restrict__ xr,
                      const float* __restrict__ att, const float* __restrict__ bout) {
    __shared__ float sred[8][128];
    int tid = threadIdx.x;
    int wid = tid >> 5;
    int lane = tid & 31;
    int warp = blockIdx.x * 8 + wid;    // NN divisible by 8: always < NN

    const float4 xrv = *(const float4*)(xr + (size_t)warp * 128 + lane * 4);
    const float4 av  = *(const float4*)(att + lane * 4);

    float a0 = 0.f, a1 = 0.f, a2 = 0.f, a3 = 0.f, s = 0.f;

    int beg = g_rowptr[warp];
    int n = g_rowptr[warp + 1] - beg;
    const int* csrc = g_csrc + beg;

    float4 b0, b1;
    if (n > 0) b0 = *(const float4*)(xl + (size_t)csrc[0] * 128 + lane * 4);
    if (n > 1) b1 = *(const float4*)(xl + (size_t)csrc[1] * 128 + lane * 4);

    for (int j = 0; j < n; j += 2) {
        float4 c0 = b0, c1 = b1;
        bool has1 = (j + 1 < n);
        if (j + 2 < n) b0 = *(const float4*)(xl + (size_t)csrc[j + 2] * 128 + lane * 4);
        if (j + 3 < n) b1 = *(const float4*)(xl + (size_t)csrc[j + 3] * 128 + lane * 4);

        float u0 = c0.x + xrv.x; u0 = fmaxf(u0, 0.2f * u0);
        float u1 = c0.y + xrv.y; u1 = fmaxf(u1, 0.2f * u1);
        float u2 = c0.z + xrv.z; u2 = fmaxf(u2, 0.2f * u2);
        float u3 = c0.w + xrv.w; u3 = fmaxf(u3, 0.2f * u3);
        float p0 = u0 * av.x + u1 * av.y + u2 * av.z + u3 * av.w;
        float w0 = c1.x + xrv.x; w0 = fmaxf(w0, 0.2f * w0);
        float w1 = c1.y + xrv.y; w1 = fmaxf(w1, 0.2f * w1);
        float w2 = c1.z + xrv.z; w2 = fmaxf(w2, 0.2f * w2);
        float w3 = c1.w + xrv.w; w3 = fmaxf(w3, 0.2f * w3);
        float p1 = w0 * av.x + w1 * av.y + w2 * av.z + w3 * av.w;

        p0 += __shfl_xor_sync(0xffffffffu, p0, 1);
        p1 += __shfl_xor_sync(0xffffffffu, p1, 1);
        p0 += __shfl_xor_sync(0xffffffffu, p0, 2);
        p1 += __shfl_xor_sync(0xffffffffu, p1, 2);
        p0 += __shfl_xor_sync(0xffffffffu, p0, 4);
        p1 += __shfl_xor_sync(0xffffffffu, p1, 4);

        float e0 = __expf(p0);
        float e1 = has1 ? __expf(p1) : 0.f;

        s  += e0 + e1;
        a0 += e0 * c0.x;
        a1 += e0 * c0.y;
        a2 += e0 * c0.z;
        a3 += e0 * c0.w;
        if (has1) {
            a0 += e1 * c1.x;
            a1 += e1 * c1.y;
            a2 += e1 * c1.z;
            a3 += e1 * c1.w;
        }
    }

    float inv = 1.f / (s + 1e-16f);
    float4 bo = *(const float4*)(bout + lane * 4);
    float4 o;
    o.x = a0 * inv + bo.x;
    o.y = a1 * inv + bo.y;
    o.z = a2 * inv + bo.z;
    o.w = a3 * inv + bo.w;
    *(float4*)(g_agg + (size_t)warp * 128 + lane * 4) = o;

    // fused per-block column partial (deterministic fixed-order tree)
    *(float4*)(&sred[wid][lane * 4]) = o;
    __syncthreads();
    if (tid < 128) {
        float t = 0.f;
        #pragma unroll
        for (int w = 0; w < 8; w++) t += sred[w][tid];
        g_colpart[(size_t)blockIdx.x * 128 + tid] = t;
    }
}

// ---------------- column mean reduction: 12500 partials -> 125 -> mean --------
__global__ void colsum_mid_k() {
    int c = threadIdx.x;           // 128 threads
    int b = blockIdx.x;            // 125 blocks
    float s0 = 0.f, s1 = 0.f, s2 = 0.f, s3 = 0.f;
    int r = b;
    for (; r + 3 * 125 < AGG_BLOCKS; r += 4 * 125) {
        s0 += g_colpart[(size_t)r * 128 + c];
        s1 += g_colpart[(size_t)(r + 125) * 128 + c];
        s2 += g_colpart[(size_t)(r + 250) * 128 + c];
        s3 += g_colpart[(size_t)(r + 375) * 128 + c];
    }
    for (; r < AGG_BLOCKS; r += 125) s0 += g_colpart[(size_t)r * 128 + c];
    g_colmid[b * 128 + c] = (s0 + s1) + (s2 + s3);
}
__global__ void colsum_fin_k() {
    int c = threadIdx.x;
    float s = 0.f;
    for (int b = 0; b < 125; b++) s += g_colmid[b * 128 + c];
    g_colmean[c] = s * (1.0f / NN);
}

// ---------------- fused pairnorm + residual + layernorm + relu ----------------
__global__ void epilogue_k(const float* __restrict__ res,
                           const float* __restrict__ lng, const float* __restrict__ lnb,
                           float* __restrict__ out, int relu) {
    int warp = (blockIdx.x * blockDim.x + threadIdx.x) >> 5;
    int lane = threadIdx.x & 31;
    if (warp >= NN) return;

    float4 a4 = *(const float4*)(g_agg + (size_t)warp * 128 + lane * 4);
    float4 cm = *(const float4*)(g_colmean + lane * 4);
    float x0 = a4.x - cm.x, x1 = a4.y - cm.y, x2 = a4.z - cm.z, x3 = a4.w - cm.w;

    float ss = x0 * x0 + x1 * x1 + x2 * x2 + x3 * x3;
    #pragma unroll
    for (int off = 16; off > 0; off >>= 1) ss += __shfl_xor_sync(0xffffffffu, ss, off);
    float l2 = sqrtf(ss) + 1e-6f;
    float sc = 316.2277660168379f / l2;

    float4 r4 = *(const float4*)(res + (size_t)warp * 128 + lane * 4);
    float h0 = x0 * sc + r4.x;
    float h1 = x1 * sc + r4.y;
    float h2 = x2 * sc + r4.z;
    float h3 = x3 * sc + r4.w;

    float sm = h0 + h1 + h2 + h3;
    #pragma unroll
    for (int off = 16; off > 0; off >>= 1) sm += __shfl_xor_sync(0xffffffffu, sm, off);
    float mu = sm * (1.0f / 128.0f);

    float d0 = h0 - mu, d1 = h1 - mu, d2 = h2 - mu, d3 = h3 - mu;
    float sv = d0 * d0 + d1 * d1 + d2 * d2 + d3 * d3;
    #pragma unroll
    for (int off = 16; off > 0; off >>= 1) sv += __shfl_xor_sync(0xffffffffu, sv, off);
    float rs = rsqrtf(sv * (1.0f / 128.0f) + 1e-5f);

    float4 g4 = *(const float4*)(lng + lane * 4);
    float4 b4 = *(const float4*)(lnb + lane * 4);
    float y0 = d0 * rs * g4.x + b4.x;
    float y1 = d1 * rs * g4.y + b4.y;
    float y2 = d2 * rs * g4.z + b4.z;
    float y3 = d3 * rs * g4.w + b4.w;
    if (relu) {
        y0 = fmaxf(y0, 0.f); y1 = fmaxf(y1, 0.f);
        y2 = fmaxf(y2, 0.f); y3 = fmaxf(y3, 0.f);
    }
    float4 o = {y0, y1, y2, y3};
    *(float4*)(out + (size_t)warp * 128 + lane * 4) = o;
}

// ---------------- host orchestration ------------------------------------------
extern "C" void kernel_launch(void* const* d_in, const int* in_sizes, int n_in,
                              void* d_out, int out_size) {
    const float* x     = (const float*)d_in[0];
    const int*   ei    = (const int*)  d_in[1];
    const float* w_in  = (const float*)d_in[2];
    const float* b_in  = (const float*)d_in[3];
    const float* Wl    = (const float*)d_in[4];
    const float* bl    = (const float*)d_in[5];
    const float* Wr    = (const float*)d_in[6];
    const float* att   = (const float*)d_in[7];
    const float* b_out = (const float*)d_in[8];
    const float* Wres  = (const float*)d_in[9];
    const float* bres  = (const float*)d_in[10];
    const float* ln_g  = (const float*)d_in[11];
    const float* ln_b  = (const float*)d_in[12];
    float* out = (float*)d_out;

    cudaFuncSetAttribute(gemm_mma_k, cudaFuncAttributeMaxDynamicSharedMemorySize, GEMM_SMEM);

    float *hp, *xlp, *xrp, *resp;
    cudaGetSymbolAddress((void**)&hp,   g_h);
    cudaGetSymbolAddress((void**)&xlp,  g_xl);
    cudaGetSymbolAddress((void**)&xrp,  g_xr);
    cudaGetSymbolAddress((void**)&resp, g_res);
    __nv_bfloat16* wcp;
    cudaGetSymbolAddress((void**)&wcp, g_wconv);

    const int GX = (NN + RT - 1) / RT;
    const size_t WSTRIDE = 2 * WIMG_ELEMS;

    // fork a side stream for the CSR build (independent of the first GEMMs)
    cudaStream_t s2;
    cudaStreamCreateWithFlags(&s2, cudaStreamNonBlocking);
    cudaEvent_t evFork, evJoin;
    cudaEventCreateWithFlags(&evFork, cudaEventDisableTiming);
    cudaEventCreateWithFlags(&evJoin, cudaEventDisableTiming);

    cudaEventRecord(evFork, 0);
    cudaStreamWaitEvent(s2, evFork, 0);

    // CSR chain on side stream
    zero_deg_k<<<(NN + 255) / 256, 256, 0, s2>>>();
    hist_k<<<(EE + 255) / 256, 256, 0, s2>>>(ei);
    scan1_k<<<SB, SC, 0, s2>>>();
    scan2_k<<<1, 256, 0, s2>>>();
    scan3_k<<<SB, SC, 0, s2>>>();
    scatter_k<<<(EE + 255) / 256, 256, 0, s2>>>(ei);
    cudaEventRecord(evJoin, s2);

    // main stream: weight conversion + first two GEMM launches
    wconv_k<<<9, 256>>>(w_in, Wl, Wr, Wres);

    // input projection: h = x @ w_in + b_in
    {
        Job j0 = {wcp, b_in, hp};
        gemm_mma_k<<<GX, 512, GEMM_SMEM>>>(x, j0, j0, j0, 1, NN);
    }
    // layer-0 GEMM (Wl, Wr)
    {
        Job j0 = {wcp + 1 * WSTRIDE, bl, xlp};
        Job j1 = {wcp + 4 * WSTRIDE, nullptr, xrp};
        gemm_mma_k<<<GX, 512, GEMM_SMEM>>>(hp, j0, j1, j1, 2, NN);
    }

    // join: CSR must be done before first agg
    cudaStreamWaitEvent(0, evJoin, 0);

    for (int i = 0; i < 3; i++) {
        if (i > 0) {
            Job j0 = {wcp + (1 + i) * WSTRIDE, bl + (size_t)i * DD, xlp};
            Job j1 = {wcp + (4 + i) * WSTRIDE, nullptr, xrp};
            Job j2 = {wcp + (7 + (i - 1)) * WSTRIDE, bres + (size_t)(i - 1) * DD, resp};
            gemm_mma_k<<<GX, 512, GEMM_SMEM>>>(hp, j0, j1, j2, 3, NN);
        }

        agg_k<<<AGG_BLOCKS, 256>>>(xlp, xrp, att + (size_t)i * DD, b_out + (size_t)i * DD);

        colsum_mid_k<<<125, 128>>>();
        colsum_fin_k<<<1, 128>>>();

        const float* rsrc = (i > 0) ? resp : hp;
        float* dst = (i == 2) ? out : hp;
        epilogue_k<<<NN / 8, 256>>>(rsrc, ln_g + (size_t)i * DD, ln_b + (size_t)i * DD,
                                    dst, (i < 2) ? 1 : 0);
    }
}